// round 7
// baseline (speedup 1.0000x reference)
#include <cuda_runtime.h>

#define C_   16
#define GX_  36
#define GY_  36
#define RF_  24
#define IMG_ 64
#define G_   (GX_ * GY_)        // 1296
#define GAMMA_E 0.9f
#define GAMMA_I 0.9f

// Combined partial per (ij,c): aff + ge*p*exc - gi*p*inh.
// Layout [ij][c]: each ij's 16 partials are one contiguous 64B span.
__device__ float g_part[G_ * C_];

__global__ __launch_bounds__(128, 16)
void cortex_partial(const float* __restrict__ x,
                    const float* __restrict__ prev,
                    const float* __restrict__ aw,
                    const float* __restrict__ ew,
                    const float* __restrict__ iw,
                    const int*   __restrict__ rx,
                    const int*   __restrict__ ry)
{
    const int ij = blockIdx.x;           // 0..1295
    const int c  = blockIdx.y;           // 0..15
    const int i  = ij / GY_;
    const int j  = ij - i * GY_;
    const int t  = threadIdx.x;

    // ---- Lateral row sums (324 float4 per tensor, streamed once) ----
    const size_t rowbase = (size_t)(c * G_ + ij) * G_;
    const float4* e4 = reinterpret_cast<const float4*>(ew + rowbase);
    const float4* i4 = reinterpret_cast<const float4*>(iw + rowbase);
    float se = 0.f, si = 0.f;
    const int NF4 = G_ / 4;              // 324
    #pragma unroll
    for (int o = t; o < NF4; o += 128) {
        const float4 ve = __ldcs(e4 + o);
        const float4 vi = __ldcs(i4 + o);
        se += (ve.x + ve.y) + (ve.z + ve.w);
        si += (vi.x + vi.y) + (vi.z + vi.w);
    }

    // ---- Afferent (144 float4, streamed once; x is L1/L2-resident) ----
    float aff = 0.f;
    const int rxi = __ldg(rx + i), ryj = __ldg(ry + j);
    const float4* a4 = reinterpret_cast<const float4*>(
        aw + (size_t)(c * G_ + ij) * (RF_ * RF_));
    #pragma unroll
    for (int o = t; o < (RF_ * RF_) / 4; o += 128) {
        const float4 w4 = __ldcs(a4 + o);
        const int uv = o * 4;
        const int u  = uv / RF_;
        const int v  = uv - u * RF_;
        const float* xr = x + c * IMG_ * IMG_ + (rxi + u) * IMG_ + (ryj + v);
        aff += w4.x * __ldg(xr + 0) + w4.y * __ldg(xr + 1)
             + w4.z * __ldg(xr + 2) + w4.w * __ldg(xr + 3);
    }

    // ---- Block reduce (128 threads = 4 warps) ----
    const unsigned FULL = 0xFFFFFFFFu;
    #pragma unroll
    for (int off = 16; off > 0; off >>= 1) {
        aff += __shfl_down_sync(FULL, aff, off);
        se  += __shfl_down_sync(FULL, se,  off);
        si  += __shfl_down_sync(FULL, si,  off);
    }
    __shared__ float s_red[3][4];
    const int wid = t >> 5, lid = t & 31;
    if (lid == 0) { s_red[0][wid] = aff; s_red[1][wid] = se; s_red[2][wid] = si; }
    __syncthreads();

    if (t == 0) {
        const float a = s_red[0][0] + s_red[0][1] + s_red[0][2] + s_red[0][3];
        const float e = s_red[1][0] + s_red[1][1] + s_red[1][2] + s_red[1][3];
        const float v = s_red[2][0] + s_red[2][1] + s_red[2][2] + s_red[2][3];
        const float p = __ldg(prev + c * G_ + ij);
        g_part[ij * C_ + c] = a + GAMMA_E * (p * e) - GAMMA_I * (p * v);
    }

    // Allow the dependent (finalize) grid to start as early as HW permits.
    asm volatile("griddepcontrol.launch_dependents;");
}

// One THREAD per ij: 6 CTAs total (minimal SM displacement under PDL).
// 4 independent float4 L2 loads per thread, sum, relu, 16 stores.
__global__ __launch_bounds__(256)
void cortex_finalize(float* __restrict__ out)
{
    const int ij = blockIdx.x * blockDim.x + threadIdx.x;

    // Wait until all memory from cortex_partial is visible.
    asm volatile("griddepcontrol.wait;" ::: "memory");

    if (ij >= G_) return;

    const float4* p4 = reinterpret_cast<const float4*>(&g_part[ij * C_]);
    const float4 a = __ldcg(p4 + 0);
    const float4 b = __ldcg(p4 + 1);
    const float4 cc = __ldcg(p4 + 2);
    const float4 d = __ldcg(p4 + 3);
    const float tot = ((a.x + a.y) + (a.z + a.w))
                    + ((b.x + b.y) + (b.z + b.w))
                    + ((cc.x + cc.y) + (cc.z + cc.w))
                    + ((d.x + d.y) + (d.z + d.w));
    const float act = fmaxf(tot, 0.f);
    #pragma unroll
    for (int c = 0; c < C_; c++)
        out[c * G_ + ij] = act;
}

extern "C" void kernel_launch(void* const* d_in, const int* in_sizes, int n_in,
                              void* d_out, int out_size)
{
    const float* x    = (const float*)d_in[0];
    const float* prev = (const float*)d_in[1];
    const float* aw   = (const float*)d_in[2];
    const float* ew   = (const float*)d_in[3];
    const float* iw   = (const float*)d_in[4];
    const int*   rx   = (const int*)d_in[5];
    const int*   ry   = (const int*)d_in[6];
    float* out = (float*)d_out;

    dim3 grid(G_, C_);
    cortex_partial<<<grid, 128>>>(x, prev, aw, ew, iw, rx, ry);

    // Finalize: 6 CTAs, one thread per ij, PDL-overlapped with partial's tail.
    const int n_cta = (G_ + 255) / 256;   // 6

    cudaLaunchConfig_t cfg = {};
    cfg.gridDim  = dim3(n_cta, 1, 1);
    cfg.blockDim = dim3(256, 1, 1);
    cfg.dynamicSmemBytes = 0;
    cudaLaunchAttribute attrs[1];
    attrs[0].id = cudaLaunchAttributeProgrammaticStreamSerialization;
    attrs[0].val.programmaticStreamSerializationAllowed = 1;
    cfg.attrs = attrs;
    cfg.numAttrs = 1;
    cudaLaunchKernelEx(&cfg, cortex_finalize, out);
}